// round 13
// baseline (speedup 1.0000x reference)
#include <cuda_runtime.h>
#include <cuda_fp16.h>
#include <math.h>
#include <math_constants.h>
#include <stdint.h>

// ---------------------------------------------------------------------------
// CircleLoss round 12: fp16 mma.sync with FP16 ACCUMULATORS (rate experiment).
//   fp32-acc legacy HMMA measured at ~24 cyc/instr/SMSP (the current wall).
//   Hypothesis: f16-acc variant dispatches at 2x. Acc regs drop 64 -> 16.
//   Finalize reverted to a separate kernel (fused version regressed twice).
//   Precision: +~1.4e-4 rms on sim from fp16 accumulation -> ~1e-4 output.
// ---------------------------------------------------------------------------

#define N_MAX    8192
#define D_DIM    256
#define BM       128
#define BN       128
#define NB       (N_MAX / BM)          // 64
#define NTILES   (NB * (NB + 1) / 2)   // 2080
#define NTHREADS 256
#define CHK      64                    // K-chunk (fp16 elems)
#define NCH      (D_DIM / CHK)         // 4
#define STRIDE   144                   // smem row stride bytes (128 + 16 pad)
#define BUF_B    (BM * STRIDE)         // 18432 per buffer
#define STAGE_B  (2 * BUF_B)           // A, B
#define GAMMA    256.0f
#define DELTA_P  0.75f
#define DELTA_N  0.25f
#define OPT_P    1.25f
#define OPT_N    0.25f
// log2-domain constants for the negative logit: gamma*(s^2 - 1/16) * log2(e)
#define C2_LOG2  369.32993046757263f   // 256 * log2(e)
#define D16_LOG2 23.083120654223289f   // 16  * log2(e)

__device__ __half g_xh[(size_t)N_MAX * D_DIM];   // 4 MB fp16 normalized
__device__ float  g_part[NTILES * 4];

__device__ __forceinline__ uint32_t smem_u32(const void* p) {
    uint32_t a;
    asm("{ .reg .u64 t; cvta.to.shared.u64 t, %1; cvt.u32.u64 %0, t; }" : "=r"(a) : "l"(p));
    return a;
}
__device__ __forceinline__ void ldm_x4(uint32_t* f, uint32_t addr) {
    asm volatile("ldmatrix.sync.aligned.m8n8.x4.shared.b16 {%0,%1,%2,%3}, [%4];"
                 : "=r"(f[0]), "=r"(f[1]), "=r"(f[2]), "=r"(f[3]) : "r"(addr));
}
// fp16-accumulator HMMA: D,C are 2 regs of packed half2 {e0,e1},{e2,e3}
__device__ __forceinline__ void mma_f16acc(uint32_t* d, const uint32_t* a, const uint32_t* b) {
    asm volatile("mma.sync.aligned.m16n8k16.row.col.f16.f16.f16.f16 "
                 "{%0,%1}, {%2,%3,%4,%5}, {%6,%7}, {%0,%1};"
                 : "+r"(d[0]), "+r"(d[1])
                 : "r"(a[0]), "r"(a[1]), "r"(a[2]), "r"(a[3]), "r"(b[0]), "r"(b[1]));
}
__device__ __forceinline__ float ex2f(float x) {
    float r;
    asm("ex2.approx.f32 %0, %1;" : "=f"(r) : "f"(x));
    return r;
}
__device__ __forceinline__ void cpasync16(uint32_t saddr, const void* g) {
    asm volatile("cp.async.cg.shared.global [%0], [%1], 16;" :: "r"(saddr), "l"(g) : "memory");
}
#define CP_COMMIT() asm volatile("cp.async.commit_group;" ::: "memory")
#define CP_WAIT1()  asm volatile("cp.async.wait_group 1;" ::: "memory")
#define CP_WAIT0()  asm volatile("cp.async.wait_group 0;" ::: "memory")

// ---------------------------------------------------------------------------
// Kernel 1: L2-normalize + fp16 convert. One warp per row, 8 rows/block.
// ---------------------------------------------------------------------------
__global__ void normalize_kernel(const float* __restrict__ e) {
    const int wid  = threadIdx.x >> 5;
    const int lane = threadIdx.x & 31;
    const int row  = blockIdx.x * 8 + wid;
    const float4* rp = (const float4*)(e + (size_t)row * D_DIM);
    const float4 v0 = rp[lane * 2];
    const float4 v1 = rp[lane * 2 + 1];
    float ss = v0.x * v0.x + v0.y * v0.y + v0.z * v0.z + v0.w * v0.w
             + v1.x * v1.x + v1.y * v1.y + v1.z * v1.z + v1.w * v1.w;
    #pragma unroll
    for (int o = 16; o > 0; o >>= 1) ss += __shfl_xor_sync(0xffffffffu, ss, o);
    const float inv = 1.0f / fmaxf(sqrtf(ss), 1e-12f);
    __half2 h[4];
    h[0] = __floats2half2_rn(v0.x * inv, v0.y * inv);
    h[1] = __floats2half2_rn(v0.z * inv, v0.w * inv);
    h[2] = __floats2half2_rn(v1.x * inv, v1.y * inv);
    h[3] = __floats2half2_rn(v1.z * inv, v1.w * inv);
    *(uint4*)(g_xh + (size_t)row * D_DIM + lane * 8) = *(const uint4*)h;
}

__device__ __forceinline__ void lse_combine(float& m, float& s, float m2, float s2) {
    const float M = fmaxf(m, m2);
    if (M == -CUDART_INF_F) return;
    s = s * __expf(m - M) + s2 * __expf(m2 - M);
    m = M;
}

// ---------------------------------------------------------------------------
// Kernel 2: one upper-triangle 128x128 tile; 8 warps (2x4), warp tile 64x32.
// fp16-acc MMA; cp.async double-buffered smem; 2 CTAs/SM.
// ---------------------------------------------------------------------------
__global__ __launch_bounds__(NTHREADS, 2)
void circle_tile_hmma(const int* __restrict__ labels) {
    extern __shared__ char dsm[];
    __shared__ int   La[BM];
    __shared__ int   Lb[BN];
    __shared__ float wred[8][4];       // per-warp (mp,sp,mn,sn)

    const int tid  = threadIdx.x;
    const int wid  = tid >> 5;
    const int lane = tid & 31;
    const int wm   = wid & 1;          // 2 warp rows x 64
    const int wn   = wid >> 1;         // 4 warp cols x 32

    const uint32_t sb = smem_u32(dsm);

    int t = blockIdx.x, bi = 0, rowLen = NB;
    while (t >= rowLen) { t -= rowLen; rowLen--; bi++; }
    const int bj = bi + t;
    const bool diag = (bi == bj);
    const int rowBase = bi * BM, colBase = bj * BN;

    if (tid < BM) La[tid]      = labels[rowBase + tid];
    else          Lb[tid - BM] = labels[colBase + (tid - BM)];

    uint32_t acc[4][4][2];             // packed half2 accumulators
    #pragma unroll
    for (int mi = 0; mi < 4; mi++)
        #pragma unroll
        for (int ni = 0; ni < 4; ni++) { acc[mi][ni][0] = 0u; acc[mi][ni][1] = 0u; }

    auto stage = [&](int c, int sbuf) {
        const uint32_t base = sb + (uint32_t)sbuf * STAGE_B;
        #pragma unroll
        for (int it = 0; it < 8; it++) {
            const int idx = tid + it * NTHREADS;
            const int buf = idx >> 10;
            const int v   = idx & 1023;
            const int r   = v >> 3;
            const int seg = v & 7;
            const int grow = (buf ? colBase : rowBase) + r;
            const __half* gp = g_xh + (size_t)grow * D_DIM + c * CHK + seg * 8;
            cpasync16(base + (uint32_t)buf * BUF_B + (uint32_t)(r * STRIDE + seg * 16), gp);
        }
        CP_COMMIT();
    };

    const int arow = (lane & 7) + ((lane >> 3) & 1) * 8;
    const int acol = (lane >> 4) * 8;
    // B x4 mapping: lanes 0-15 -> n 0-7 (k 0/8), lanes 16-31 -> n 8-15
    const int bro  = ((lane >> 4) & 1) * 8 + (lane & 7);
    const int bkc  = ((lane >> 3) & 1) * 8;

    stage(0, 0);
    for (int c = 0; c < NCH; c++) {
        if (c < NCH - 1) { stage(c + 1, (c + 1) & 1); CP_WAIT1(); }
        else             { CP_WAIT0(); }
        __syncthreads();

        const uint32_t S  = sb + (uint32_t)(c & 1) * STAGE_B;
        const uint32_t Sa = S, Sb = S + BUF_B;

        #pragma unroll
        for (int ks = 0; ks < CHK / 16; ks++) {
            const int k0 = ks * 16;
            uint32_t af[4][4], bf[4][2];
            #pragma unroll
            for (int mi = 0; mi < 4; mi++) {
                const uint32_t ro = (uint32_t)((wm * 64 + mi * 16 + arow) * STRIDE + (k0 + acol) * 2);
                ldm_x4(af[mi], Sa + ro);
            }
            #pragma unroll
            for (int np = 0; np < 2; np++) {   // ni pairs (0,1) and (2,3)
                const uint32_t ro = (uint32_t)((wn * 32 + np * 16 + bro) * STRIDE + (k0 + bkc) * 2);
                ldm_x4(&bf[np * 2][0], Sb + ro);
            }
            #pragma unroll
            for (int mi = 0; mi < 4; mi++)
                #pragma unroll
                for (int ni = 0; ni < 4; ni++)
                    mma_f16acc(acc[mi][ni], af[mi], bf[ni]);
        }
        __syncthreads();
    }

    // ---- epilogue (unpack fp16 acc on the fly) ----
    int liA[8], ljB[8];
    #pragma unroll
    for (int mi = 0; mi < 4; mi++) {
        liA[mi * 2]     = La[wm * 64 + mi * 16 + (lane >> 2)];
        liA[mi * 2 + 1] = La[wm * 64 + mi * 16 + (lane >> 2) + 8];
    }
    #pragma unroll
    for (int ni = 0; ni < 4; ni++) {
        ljB[ni * 2]     = Lb[wn * 32 + ni * 8 + (lane & 3) * 2];
        ljB[ni * 2 + 1] = Lb[wn * 32 + ni * 8 + (lane & 3) * 2 + 1];
    }

    float mp = -CUDART_INF_F, sp = 0.f, mn, sn;

    if (!diag) {
        // FAST single-pass path: negatives via en = 2^(C2*t^2 - D16),
        // t = max(s, -1/4); 4 independent partial sums.
        // Positives (rare): predicated online LSE.
        float ns0 = 0.f, ns1 = 0.f, ns2 = 0.f, ns3 = 0.f;
        #pragma unroll
        for (int mi = 0; mi < 4; mi++)
            #pragma unroll
            for (int ni = 0; ni < 4; ni++) {
                const float2 p01 = __half22float2(*(const __half2*)&acc[mi][ni][0]);
                const float2 p23 = __half22float2(*(const __half2*)&acc[mi][ni][1]);
                const float sv[4] = { p01.x, p01.y, p23.x, p23.y };
                #pragma unroll
                for (int e = 0; e < 4; e++) {
                    const float s = sv[e];
                    const bool pos = (liA[mi * 2 + (e >> 1)] == ljB[ni * 2 + (e & 1)]);
                    const float tt = fmaxf(s, -OPT_N);
                    const float en = ex2f(fmaf(tt * C2_LOG2, tt, -D16_LOG2));
                    if (!pos) {
                        if      (e == 0) ns0 += en;
                        else if (e == 1) ns1 += en;
                        else if (e == 2) ns2 += en;
                        else             ns3 += en;
                    } else {                       // rare
                        const float lp = -GAMMA * fmaxf(OPT_P - s, 0.f) * (s - DELTA_P);
                        if (lp > mp) { sp = sp * __expf(mp - lp) + 1.f; mp = lp; }
                        else         { sp += __expf(lp - mp); }
                    }
                }
            }
        sp *= 2.0f;                // off-diag tiles count twice (symmetry)
        mn = 0.f;
        sn = ((ns0 + ns1) + (ns2 + ns3)) * 2.0f;
    } else {
        // SAFE online path for diagonal tiles, weight 1, excl. i==j.
        float mnl = -CUDART_INF_F, snl = 0.f;
        #pragma unroll
        for (int mi = 0; mi < 4; mi++)
            #pragma unroll
            for (int ni = 0; ni < 4; ni++) {
                const float2 p01 = __half22float2(*(const __half2*)&acc[mi][ni][0]);
                const float2 p23 = __half22float2(*(const __half2*)&acc[mi][ni][1]);
                const float sv[4] = { p01.x, p01.y, p23.x, p23.y };
                #pragma unroll
                for (int e = 0; e < 4; e++) {
                    const int row = wm * 64 + mi * 16 + (lane >> 2) + (e >> 1) * 8;
                    const int col = wn * 32 + ni * 8 + (lane & 3) * 2 + (e & 1);
                    const float s = sv[e];
                    const bool pos = (liA[mi * 2 + (e >> 1)] == ljB[ni * 2 + (e & 1)]);
                    if (pos) {
                        if (row == col) continue;          // exclude diagonal
                        const float lp = -GAMMA * fmaxf(OPT_P - s, 0.f) * (s - DELTA_P);
                        if (lp > mp) { sp = sp * __expf(mp - lp) + 1.f; mp = lp; }
                        else         { sp += __expf(lp - mp); }
                    } else {
                        const float ln = GAMMA * fmaxf(s + OPT_N, 0.f) * (s - DELTA_N);
                        if (ln > mnl) { snl = snl * __expf(mnl - ln) + 1.f; mnl = ln; }
                        else          { snl += __expf(ln - mnl); }
                    }
                }
            }
        mn = (mnl < -1e37f) ? 0.f : mnl;
        sn = snl;
    }

    // warp shuffle LSE reduction
    #pragma unroll
    for (int o = 16; o > 0; o >>= 1) {
        const float mp2 = __shfl_xor_sync(0xffffffffu, mp, o);
        const float sp2 = __shfl_xor_sync(0xffffffffu, sp, o);
        const float mn2 = __shfl_xor_sync(0xffffffffu, mn, o);
        const float sn2 = __shfl_xor_sync(0xffffffffu, sn, o);
        lse_combine(mp, sp, mp2, sp2);
        lse_combine(mn, sn, mn2, sn2);
    }
    if (lane == 0) {
        wred[wid][0] = mp; wred[wid][1] = sp;
        wred[wid][2] = mn; wred[wid][3] = sn;
    }
    __syncthreads();
    if (tid == 0) {
        float Mp = wred[0][0], Sp = wred[0][1], Mn = wred[0][2], Sn = wred[0][3];
        #pragma unroll
        for (int w = 1; w < 8; w++) {
            lse_combine(Mp, Sp, wred[w][0], wred[w][1]);
            lse_combine(Mn, Sn, wred[w][2], wred[w][3]);
        }
        const int bid = blockIdx.x;
        g_part[bid * 4 + 0] = Mp; g_part[bid * 4 + 1] = Sp;
        g_part[bid * 4 + 2] = Mn; g_part[bid * 4 + 3] = Sn;
    }
}

// ---------------------------------------------------------------------------
// Kernel 3: combine partials, softplus, write scalar.
// ---------------------------------------------------------------------------
__global__ void finalize_kernel(float* __restrict__ out, int nPart) {
    const int t = threadIdx.x;
    float mp = -CUDART_INF_F, sp = 0.f, mn = -CUDART_INF_F, sn = 0.f;
    for (int i = t; i < nPart; i += blockDim.x) {
        const float4 v = *(const float4*)(g_part + i * 4);
        lse_combine(mp, sp, v.x, v.y);
        lse_combine(mn, sn, v.z, v.w);
    }
    __shared__ float rm[256], rs[256];
    __shared__ float lse_p;
    rm[t] = mp; rs[t] = sp; __syncthreads();
    for (int off = 128; off > 0; off >>= 1) {
        if (t < off) {
            float m = rm[t], s = rs[t];
            lse_combine(m, s, rm[t + off], rs[t + off]);
            rm[t] = m; rs[t] = s;
        }
        __syncthreads();
    }
    if (t == 0) lse_p = rm[0] + logf(rs[0]);
    __syncthreads();
    rm[t] = mn; rs[t] = sn; __syncthreads();
    for (int off = 128; off > 0; off >>= 1) {
        if (t < off) {
            float m = rm[t], s = rs[t];
            lse_combine(m, s, rm[t + off], rs[t + off]);
            rm[t] = m; rs[t] = s;
        }
        __syncthreads();
    }
    if (t == 0) {
        const float x = lse_p + rm[0] + logf(rs[0]);
        out[0] = (x > 20.f) ? x : log1pf(expf(x));
    }
}

// ---------------------------------------------------------------------------
extern "C" void kernel_launch(void* const* d_in, const int* in_sizes, int n_in,
                              void* d_out, int out_size) {
    const float* emb    = (const float*)d_in[0];
    const int*   labels = (const int*)d_in[1];
    float*       out    = (float*)d_out;

    const int B = in_sizes[1];            // 8192
    const int dyn = 2 * STAGE_B;          // 73728 bytes

    cudaFuncSetAttribute(circle_tile_hmma, cudaFuncAttributeMaxDynamicSharedMemorySize, dyn);

    normalize_kernel<<<B / 8, 256>>>(emb);
    circle_tile_hmma<<<NTILES, NTHREADS, dyn>>>(labels);
    finalize_kernel<<<1, 256>>>(out, NTILES);
}

// round 14
// speedup vs baseline: 1.1304x; 1.1304x over previous
#include <cuda_runtime.h>
#include <cuda_fp16.h>
#include <math.h>
#include <math_constants.h>
#include <stdint.h>

// ---------------------------------------------------------------------------
// CircleLoss round 13: fp32-acc fp16 HMMA, 64x128 tiles, 3 CTAs/SM.
//   R10 champion + finer tiling: tail-wave overhead 12% -> ~6%, and smaller
//   acc footprint (32 regs) allows 3-way CTA overlap to hide the epilogue.
//   Tiles: col-block j (128 wide), row-block i (64 tall), i <= 2j+1;
//   id = j(j+1)+i; straddle tiles (i>=2j) use strict-upper mask, weight 2.
// ---------------------------------------------------------------------------

#define N_MAX    8192
#define D_DIM    256
#define BM       64                    // tile rows (A)
#define BN       128                   // tile cols (B)
#define NBJ      (N_MAX / BN)          // 64 col blocks
#define NTILES   (NBJ * (NBJ + 1))     // 4160
#define NTHREADS 256
#define CHK      64                    // K-chunk (fp16 elems)
#define NCH      (D_DIM / CHK)         // 4
#define STRIDE   144                   // smem row stride bytes (128 + 16 pad)
#define BUFA_B   (BM * STRIDE)         // 9216
#define BUFB_B   (BN * STRIDE)         // 18432
#define STAGE_B  (BUFA_B + BUFB_B)     // 27648
#define GAMMA    256.0f
#define DELTA_P  0.75f
#define OPT_P    1.25f
#define OPT_N    0.25f
// log2-domain constants for the negative logit: gamma*(s^2 - 1/16) * log2(e)
#define C2_LOG2  369.32993046757263f   // 256 * log2(e)
#define D16_LOG2 23.083120654223289f   // 16  * log2(e)

__device__ __half g_xh[(size_t)N_MAX * D_DIM];   // 4 MB fp16 normalized
__device__ float  g_part[NTILES * 4];

__device__ __forceinline__ uint32_t smem_u32(const void* p) {
    uint32_t a;
    asm("{ .reg .u64 t; cvta.to.shared.u64 t, %1; cvt.u32.u64 %0, t; }" : "=r"(a) : "l"(p));
    return a;
}
__device__ __forceinline__ void ldm_x4(uint32_t* f, uint32_t addr) {
    asm volatile("ldmatrix.sync.aligned.m8n8.x4.shared.b16 {%0,%1,%2,%3}, [%4];"
                 : "=r"(f[0]), "=r"(f[1]), "=r"(f[2]), "=r"(f[3]) : "r"(addr));
}
__device__ __forceinline__ void mma_f16(float* d, const uint32_t* a, const uint32_t* b) {
    asm volatile("mma.sync.aligned.m16n8k16.row.col.f32.f16.f16.f32 "
                 "{%0,%1,%2,%3}, {%4,%5,%6,%7}, {%8,%9}, {%0,%1,%2,%3};"
                 : "+f"(d[0]), "+f"(d[1]), "+f"(d[2]), "+f"(d[3])
                 : "r"(a[0]), "r"(a[1]), "r"(a[2]), "r"(a[3]), "r"(b[0]), "r"(b[1]));
}
__device__ __forceinline__ float ex2f(float x) {
    float r;
    asm("ex2.approx.f32 %0, %1;" : "=f"(r) : "f"(x));
    return r;
}
__device__ __forceinline__ void cpasync16(uint32_t saddr, const void* g) {
    asm volatile("cp.async.cg.shared.global [%0], [%1], 16;" :: "r"(saddr), "l"(g) : "memory");
}
#define CP_COMMIT() asm volatile("cp.async.commit_group;" ::: "memory")
#define CP_WAIT1()  asm volatile("cp.async.wait_group 1;" ::: "memory")
#define CP_WAIT0()  asm volatile("cp.async.wait_group 0;" ::: "memory")

// ---------------------------------------------------------------------------
// Kernel 1: L2-normalize + fp16 convert. One warp per row, 8 rows/block.
// ---------------------------------------------------------------------------
__global__ void normalize_kernel(const float* __restrict__ e) {
    const int wid  = threadIdx.x >> 5;
    const int lane = threadIdx.x & 31;
    const int row  = blockIdx.x * 8 + wid;
    const float4* rp = (const float4*)(e + (size_t)row * D_DIM);
    const float4 v0 = rp[lane * 2];
    const float4 v1 = rp[lane * 2 + 1];
    float ss = v0.x * v0.x + v0.y * v0.y + v0.z * v0.z + v0.w * v0.w
             + v1.x * v1.x + v1.y * v1.y + v1.z * v1.z + v1.w * v1.w;
    #pragma unroll
    for (int o = 16; o > 0; o >>= 1) ss += __shfl_xor_sync(0xffffffffu, ss, o);
    const float inv = 1.0f / fmaxf(sqrtf(ss), 1e-12f);
    __half2 h[4];
    h[0] = __floats2half2_rn(v0.x * inv, v0.y * inv);
    h[1] = __floats2half2_rn(v0.z * inv, v0.w * inv);
    h[2] = __floats2half2_rn(v1.x * inv, v1.y * inv);
    h[3] = __floats2half2_rn(v1.z * inv, v1.w * inv);
    *(uint4*)(g_xh + (size_t)row * D_DIM + lane * 8) = *(const uint4*)h;
}

__device__ __forceinline__ void lse_combine(float& m, float& s, float m2, float s2) {
    const float M = fmaxf(m, m2);
    if (M == -CUDART_INF_F) return;
    s = s * __expf(m - M) + s2 * __expf(m2 - M);
    m = M;
}

// ---------------------------------------------------------------------------
// Kernel 2: one 64x128 tile; 8 warps (2x4), warp tile 32x32.
// fp32-acc fp16 MMA; cp.async double-buffered; 3 CTAs/SM.
// ---------------------------------------------------------------------------
__global__ __launch_bounds__(NTHREADS, 3)
void circle_tile_hmma(const int* __restrict__ labels) {
    extern __shared__ char dsm[];
    __shared__ int   La[BM];
    __shared__ int   Lb[BN];
    __shared__ float wred[8][4];       // per-warp (mp,sp,mn,sn)

    const int tid  = threadIdx.x;
    const int wid  = tid >> 5;
    const int lane = tid & 31;
    const int wm   = wid & 1;          // 2 warp rows x 32
    const int wn   = wid >> 1;         // 4 warp cols x 32

    const uint32_t sb = smem_u32(dsm);

    // tile id -> (j, i):  id = j*(j+1) + i,  0 <= i <= 2j+1
    const int id = blockIdx.x;
    int j = (int)((sqrtf(4.f * (float)id + 1.f) - 1.f) * 0.5f);
    while (j * (j + 1) > id) j--;
    while ((j + 1) * (j + 2) <= id) j++;
    const int i = id - j * (j + 1);
    const bool straddle = (i >= 2 * j);          // tile touches the diagonal
    const int rowBase = i * BM, colBase = j * BN;

    if (tid < BM)            La[tid]       = labels[rowBase + tid];
    else if (tid < BM + BN)  Lb[tid - BM]  = labels[colBase + (tid - BM)];

    float acc[2][4][4];
    #pragma unroll
    for (int mi = 0; mi < 2; mi++)
        #pragma unroll
        for (int ni = 0; ni < 4; ni++)
            #pragma unroll
            for (int e = 0; e < 4; e++) acc[mi][ni][e] = 0.f;

    // stage chunk c: A = 64 rows (512 segs), B = 128 rows (1024 segs)
    auto stage = [&](int c, int sbuf) {
        const uint32_t base = sb + (uint32_t)sbuf * STAGE_B;
        #pragma unroll
        for (int it = 0; it < 6; it++) {
            const int idx = tid + it * NTHREADS;   // 0..1535
            int r, seg, grow;
            uint32_t dst;
            if (idx < 512) {
                r = idx >> 3; seg = idx & 7;
                grow = rowBase + r;
                dst = base + (uint32_t)(r * STRIDE + seg * 16);
            } else {
                const int v = idx - 512;
                r = v >> 3; seg = v & 7;
                grow = colBase + r;
                dst = base + BUFA_B + (uint32_t)(r * STRIDE + seg * 16);
            }
            const __half* gp = g_xh + (size_t)grow * D_DIM + c * CHK + seg * 8;
            cpasync16(dst, gp);
        }
        CP_COMMIT();
    };

    const int arow = (lane & 7) + ((lane >> 3) & 1) * 8;
    const int acol = (lane >> 4) * 8;
    // B x4 mapping: lanes 0-15 -> n 0-7 (k 0/8), lanes 16-31 -> n 8-15
    const int bro  = ((lane >> 4) & 1) * 8 + (lane & 7);
    const int bkc  = ((lane >> 3) & 1) * 8;

    stage(0, 0);
    for (int c = 0; c < NCH; c++) {
        if (c < NCH - 1) { stage(c + 1, (c + 1) & 1); CP_WAIT1(); }
        else             { CP_WAIT0(); }
        __syncthreads();

        const uint32_t S  = sb + (uint32_t)(c & 1) * STAGE_B;
        const uint32_t Sa = S, Sb = S + BUFA_B;

        #pragma unroll
        for (int ks = 0; ks < CHK / 16; ks++) {
            const int k0 = ks * 16;
            uint32_t af[2][4], bf[4][2];
            #pragma unroll
            for (int mi = 0; mi < 2; mi++) {
                const uint32_t ro = (uint32_t)((wm * 32 + mi * 16 + arow) * STRIDE + (k0 + acol) * 2);
                ldm_x4(af[mi], Sa + ro);
            }
            #pragma unroll
            for (int np = 0; np < 2; np++) {   // ni pairs (0,1) and (2,3)
                const uint32_t ro = (uint32_t)((wn * 32 + np * 16 + bro) * STRIDE + (k0 + bkc) * 2);
                ldm_x4(&bf[np * 2][0], Sb + ro);
            }
            #pragma unroll
            for (int mi = 0; mi < 2; mi++)
                #pragma unroll
                for (int ni = 0; ni < 4; ni++)
                    mma_f16(acc[mi][ni], af[mi], bf[ni]);
        }
        __syncthreads();
    }

    // ---- epilogue ----
    int liA[4], ljB[8];
    #pragma unroll
    for (int mi = 0; mi < 2; mi++) {
        liA[mi * 2]     = La[wm * 32 + mi * 16 + (lane >> 2)];
        liA[mi * 2 + 1] = La[wm * 32 + mi * 16 + (lane >> 2) + 8];
    }
    #pragma unroll
    for (int ni = 0; ni < 4; ni++) {
        ljB[ni * 2]     = Lb[wn * 32 + ni * 8 + (lane & 3) * 2];
        ljB[ni * 2 + 1] = Lb[wn * 32 + ni * 8 + (lane & 3) * 2 + 1];
    }

    float mp = -CUDART_INF_F, sp = 0.f;
    float ns0 = 0.f, ns1 = 0.f, ns2 = 0.f, ns3 = 0.f;

    if (!straddle) {
        // FAST path (97% of tiles): strictly-upper tile, weight 2.
        #pragma unroll
        for (int mi = 0; mi < 2; mi++)
            #pragma unroll
            for (int ni = 0; ni < 4; ni++)
                #pragma unroll
                for (int e = 0; e < 4; e++) {
                    const float s = acc[mi][ni][e];
                    const bool pos = (liA[mi * 2 + (e >> 1)] == ljB[ni * 2 + (e & 1)]);
                    const float tt = fmaxf(s, -OPT_N);
                    const float en = ex2f(fmaf(tt * C2_LOG2, tt, -D16_LOG2));
                    if (!pos) {
                        if      (e == 0) ns0 += en;
                        else if (e == 1) ns1 += en;
                        else if (e == 2) ns2 += en;
                        else             ns3 += en;
                    } else {
                        const float lp = -GAMMA * fmaxf(OPT_P - s, 0.f) * (s - DELTA_P);
                        if (lp > mp) { sp = sp * __expf(mp - lp) + 1.f; mp = lp; }
                        else         { sp += __expf(lp - mp); }
                    }
                }
    } else {
        // STRADDLE path (3%): include only col > row (strict upper), weight 2.
        #pragma unroll
        for (int mi = 0; mi < 2; mi++)
            #pragma unroll
            for (int ni = 0; ni < 4; ni++)
                #pragma unroll
                for (int e = 0; e < 4; e++) {
                    const int row = rowBase + wm * 32 + mi * 16 + (lane >> 2) + (e >> 1) * 8;
                    const int col = colBase + wn * 32 + ni * 8 + (lane & 3) * 2 + (e & 1);
                    if (col <= row) continue;
                    const float s = acc[mi][ni][e];
                    const bool pos = (liA[mi * 2 + (e >> 1)] == ljB[ni * 2 + (e & 1)]);
                    const float tt = fmaxf(s, -OPT_N);
                    const float en = ex2f(fmaf(tt * C2_LOG2, tt, -D16_LOG2));
                    if (!pos) {
                        ns0 += en;
                    } else {
                        const float lp = -GAMMA * fmaxf(OPT_P - s, 0.f) * (s - DELTA_P);
                        if (lp > mp) { sp = sp * __expf(mp - lp) + 1.f; mp = lp; }
                        else         { sp += __expf(lp - mp); }
                    }
                }
    }

    sp *= 2.0f;
    float mn = 0.f;
    float sn = ((ns0 + ns1) + (ns2 + ns3)) * 2.0f;

    // warp shuffle LSE reduction
    #pragma unroll
    for (int o = 16; o > 0; o >>= 1) {
        const float mp2 = __shfl_xor_sync(0xffffffffu, mp, o);
        const float sp2 = __shfl_xor_sync(0xffffffffu, sp, o);
        const float mn2 = __shfl_xor_sync(0xffffffffu, mn, o);
        const float sn2 = __shfl_xor_sync(0xffffffffu, sn, o);
        lse_combine(mp, sp, mp2, sp2);
        lse_combine(mn, sn, mn2, sn2);
    }
    if (lane == 0) {
        wred[wid][0] = mp; wred[wid][1] = sp;
        wred[wid][2] = mn; wred[wid][3] = sn;
    }
    __syncthreads();
    if (tid == 0) {
        float Mp = wred[0][0], Sp = wred[0][1], Mn = wred[0][2], Sn = wred[0][3];
        #pragma unroll
        for (int w = 1; w < 8; w++) {
            lse_combine(Mp, Sp, wred[w][0], wred[w][1]);
            lse_combine(Mn, Sn, wred[w][2], wred[w][3]);
        }
        const int bid = blockIdx.x;
        g_part[bid * 4 + 0] = Mp; g_part[bid * 4 + 1] = Sp;
        g_part[bid * 4 + 2] = Mn; g_part[bid * 4 + 3] = Sn;
    }
}

// ---------------------------------------------------------------------------
// Kernel 3: combine partials, softplus, write scalar.
// ---------------------------------------------------------------------------
__global__ void finalize_kernel(float* __restrict__ out, int nPart) {
    const int t = threadIdx.x;
    float mp = -CUDART_INF_F, sp = 0.f, mn = -CUDART_INF_F, sn = 0.f;
    for (int i = t; i < nPart; i += blockDim.x) {
        const float4 v = *(const float4*)(g_part + i * 4);
        lse_combine(mp, sp, v.x, v.y);
        lse_combine(mn, sn, v.z, v.w);
    }
    __shared__ float rm[256], rs[256];
    __shared__ float lse_p;
    rm[t] = mp; rs[t] = sp; __syncthreads();
    for (int off = 128; off > 0; off >>= 1) {
        if (t < off) {
            float m = rm[t], s = rs[t];
            lse_combine(m, s, rm[t + off], rs[t + off]);
            rm[t] = m; rs[t] = s;
        }
        __syncthreads();
    }
    if (t == 0) lse_p = rm[0] + logf(rs[0]);
    __syncthreads();
    rm[t] = mn; rs[t] = sn; __syncthreads();
    for (int off = 128; off > 0; off >>= 1) {
        if (t < off) {
            float m = rm[t], s = rs[t];
            lse_combine(m, s, rm[t + off], rs[t + off]);
            rm[t] = m; rs[t] = s;
        }
        __syncthreads();
    }
    if (t == 0) {
        const float x = lse_p + rm[0] + logf(rs[0]);
        out[0] = (x > 20.f) ? x : log1pf(expf(x));
    }
}

// ---------------------------------------------------------------------------
extern "C" void kernel_launch(void* const* d_in, const int* in_sizes, int n_in,
                              void* d_out, int out_size) {
    const float* emb    = (const float*)d_in[0];
    const int*   labels = (const int*)d_in[1];
    float*       out    = (float*)d_out;

    const int B = in_sizes[1];            // 8192
    const int dyn = 2 * STAGE_B;          // 55296 bytes

    cudaFuncSetAttribute(circle_tile_hmma, cudaFuncAttributeMaxDynamicSharedMemorySize, dyn);

    normalize_kernel<<<B / 8, 256>>>(emb);
    circle_tile_hmma<<<NTILES, NTHREADS, dyn>>>(labels);
    finalize_kernel<<<1, 256>>>(out, NTILES);
}

// round 15
// speedup vs baseline: 1.1792x; 1.0432x over previous
#include <cuda_runtime.h>
#include <cuda_fp16.h>
#include <math.h>
#include <math_constants.h>
#include <stdint.h>

// ---------------------------------------------------------------------------
// CircleLoss round 14: R14 champion tile kernel (untouched) + faster aux.
//   - normalize: 2 rows/warp -> 2 independent shuffle chains (latency overlap)
//   - finalize: 512 threads, shuffle-first reduction
//   Tile kernel is at the legacy-HMMA dispatch asymptote (~22-23 cyc/instr).
// ---------------------------------------------------------------------------

#define N_MAX    8192
#define D_DIM    256
#define BM       64                    // tile rows (A)
#define BN       128                   // tile cols (B)
#define NBJ      (N_MAX / BN)          // 64 col blocks
#define NTILES   (NBJ * (NBJ + 1))     // 4160
#define NTHREADS 256
#define CHK      64                    // K-chunk (fp16 elems)
#define NCH      (D_DIM / CHK)         // 4
#define STRIDE   144                   // smem row stride bytes (128 + 16 pad)
#define BUFA_B   (BM * STRIDE)         // 9216
#define BUFB_B   (BN * STRIDE)         // 18432
#define STAGE_B  (BUFA_B + BUFB_B)     // 27648
#define GAMMA    256.0f
#define DELTA_P  0.75f
#define OPT_P    1.25f
#define OPT_N    0.25f
// log2-domain constants for the negative logit: gamma*(s^2 - 1/16) * log2(e)
#define C2_LOG2  369.32993046757263f   // 256 * log2(e)
#define D16_LOG2 23.083120654223289f   // 16  * log2(e)

__device__ __half g_xh[(size_t)N_MAX * D_DIM];   // 4 MB fp16 normalized
__device__ float  g_part[NTILES * 4];

__device__ __forceinline__ uint32_t smem_u32(const void* p) {
    uint32_t a;
    asm("{ .reg .u64 t; cvta.to.shared.u64 t, %1; cvt.u32.u64 %0, t; }" : "=r"(a) : "l"(p));
    return a;
}
__device__ __forceinline__ void ldm_x4(uint32_t* f, uint32_t addr) {
    asm volatile("ldmatrix.sync.aligned.m8n8.x4.shared.b16 {%0,%1,%2,%3}, [%4];"
                 : "=r"(f[0]), "=r"(f[1]), "=r"(f[2]), "=r"(f[3]) : "r"(addr));
}
__device__ __forceinline__ void mma_f16(float* d, const uint32_t* a, const uint32_t* b) {
    asm volatile("mma.sync.aligned.m16n8k16.row.col.f32.f16.f16.f32 "
                 "{%0,%1,%2,%3}, {%4,%5,%6,%7}, {%8,%9}, {%0,%1,%2,%3};"
                 : "+f"(d[0]), "+f"(d[1]), "+f"(d[2]), "+f"(d[3])
                 : "r"(a[0]), "r"(a[1]), "r"(a[2]), "r"(a[3]), "r"(b[0]), "r"(b[1]));
}
__device__ __forceinline__ float ex2f(float x) {
    float r;
    asm("ex2.approx.f32 %0, %1;" : "=f"(r) : "f"(x));
    return r;
}
__device__ __forceinline__ void cpasync16(uint32_t saddr, const void* g) {
    asm volatile("cp.async.cg.shared.global [%0], [%1], 16;" :: "r"(saddr), "l"(g) : "memory");
}
#define CP_COMMIT() asm volatile("cp.async.commit_group;" ::: "memory")
#define CP_WAIT1()  asm volatile("cp.async.wait_group 1;" ::: "memory")
#define CP_WAIT0()  asm volatile("cp.async.wait_group 0;" ::: "memory")

// ---------------------------------------------------------------------------
// Kernel 1: L2-normalize + fp16 convert. TWO rows per warp (latency overlap).
// ---------------------------------------------------------------------------
__global__ void normalize_kernel(const float* __restrict__ e) {
    const int wid  = threadIdx.x >> 5;      // 8 warps -> 16 rows per block
    const int lane = threadIdx.x & 31;
    const int row0 = blockIdx.x * 16 + wid * 2;
    const float4* rp0 = (const float4*)(e + (size_t)row0 * D_DIM);
    const float4* rp1 = (const float4*)(e + (size_t)(row0 + 1) * D_DIM);
    const float4 a0 = rp0[lane * 2];
    const float4 a1 = rp0[lane * 2 + 1];
    const float4 b0 = rp1[lane * 2];
    const float4 b1 = rp1[lane * 2 + 1];
    float s0 = a0.x * a0.x + a0.y * a0.y + a0.z * a0.z + a0.w * a0.w
             + a1.x * a1.x + a1.y * a1.y + a1.z * a1.z + a1.w * a1.w;
    float s1 = b0.x * b0.x + b0.y * b0.y + b0.z * b0.z + b0.w * b0.w
             + b1.x * b1.x + b1.y * b1.y + b1.z * b1.z + b1.w * b1.w;
    #pragma unroll
    for (int o = 16; o > 0; o >>= 1) {
        s0 += __shfl_xor_sync(0xffffffffu, s0, o);
        s1 += __shfl_xor_sync(0xffffffffu, s1, o);
    }
    const float inv0 = 1.0f / fmaxf(sqrtf(s0), 1e-12f);
    const float inv1 = 1.0f / fmaxf(sqrtf(s1), 1e-12f);
    __half2 h0[4], h1[4];
    h0[0] = __floats2half2_rn(a0.x * inv0, a0.y * inv0);
    h0[1] = __floats2half2_rn(a0.z * inv0, a0.w * inv0);
    h0[2] = __floats2half2_rn(a1.x * inv0, a1.y * inv0);
    h0[3] = __floats2half2_rn(a1.z * inv0, a1.w * inv0);
    h1[0] = __floats2half2_rn(b0.x * inv1, b0.y * inv1);
    h1[1] = __floats2half2_rn(b0.z * inv1, b0.w * inv1);
    h1[2] = __floats2half2_rn(b1.x * inv1, b1.y * inv1);
    h1[3] = __floats2half2_rn(b1.z * inv1, b1.w * inv1);
    *(uint4*)(g_xh + (size_t)row0 * D_DIM + lane * 8)       = *(const uint4*)h0;
    *(uint4*)(g_xh + (size_t)(row0 + 1) * D_DIM + lane * 8) = *(const uint4*)h1;
}

__device__ __forceinline__ void lse_combine(float& m, float& s, float m2, float s2) {
    const float M = fmaxf(m, m2);
    if (M == -CUDART_INF_F) return;
    s = s * __expf(m - M) + s2 * __expf(m2 - M);
    m = M;
}

// ---------------------------------------------------------------------------
// Kernel 2: one 64x128 tile; 8 warps (2x4), warp tile 32x32.
// fp32-acc fp16 MMA; cp.async double-buffered; 3 CTAs/SM.  (R14, unchanged)
// ---------------------------------------------------------------------------
__global__ __launch_bounds__(NTHREADS, 3)
void circle_tile_hmma(const int* __restrict__ labels) {
    extern __shared__ char dsm[];
    __shared__ int   La[BM];
    __shared__ int   Lb[BN];
    __shared__ float wred[8][4];       // per-warp (mp,sp,mn,sn)

    const int tid  = threadIdx.x;
    const int wid  = tid >> 5;
    const int lane = tid & 31;
    const int wm   = wid & 1;          // 2 warp rows x 32
    const int wn   = wid >> 1;         // 4 warp cols x 32

    const uint32_t sb = smem_u32(dsm);

    // tile id -> (j, i):  id = j*(j+1) + i,  0 <= i <= 2j+1
    const int id = blockIdx.x;
    int j = (int)((sqrtf(4.f * (float)id + 1.f) - 1.f) * 0.5f);
    while (j * (j + 1) > id) j--;
    while ((j + 1) * (j + 2) <= id) j++;
    const int i = id - j * (j + 1);
    const bool straddle = (i >= 2 * j);          // tile touches the diagonal
    const int rowBase = i * BM, colBase = j * BN;

    if (tid < BM)            La[tid]       = labels[rowBase + tid];
    else if (tid < BM + BN)  Lb[tid - BM]  = labels[colBase + (tid - BM)];

    float acc[2][4][4];
    #pragma unroll
    for (int mi = 0; mi < 2; mi++)
        #pragma unroll
        for (int ni = 0; ni < 4; ni++)
            #pragma unroll
            for (int e = 0; e < 4; e++) acc[mi][ni][e] = 0.f;

    // stage chunk c: A = 64 rows (512 segs), B = 128 rows (1024 segs)
    auto stage = [&](int c, int sbuf) {
        const uint32_t base = sb + (uint32_t)sbuf * STAGE_B;
        #pragma unroll
        for (int it = 0; it < 6; it++) {
            const int idx = tid + it * NTHREADS;   // 0..1535
            int r, seg, grow;
            uint32_t dst;
            if (idx < 512) {
                r = idx >> 3; seg = idx & 7;
                grow = rowBase + r;
                dst = base + (uint32_t)(r * STRIDE + seg * 16);
            } else {
                const int v = idx - 512;
                r = v >> 3; seg = v & 7;
                grow = colBase + r;
                dst = base + BUFA_B + (uint32_t)(r * STRIDE + seg * 16);
            }
            const __half* gp = g_xh + (size_t)grow * D_DIM + c * CHK + seg * 8;
            cpasync16(dst, gp);
        }
        CP_COMMIT();
    };

    const int arow = (lane & 7) + ((lane >> 3) & 1) * 8;
    const int acol = (lane >> 4) * 8;
    // B x4 mapping: lanes 0-15 -> n 0-7 (k 0/8), lanes 16-31 -> n 8-15
    const int bro  = ((lane >> 4) & 1) * 8 + (lane & 7);
    const int bkc  = ((lane >> 3) & 1) * 8;

    stage(0, 0);
    for (int c = 0; c < NCH; c++) {
        if (c < NCH - 1) { stage(c + 1, (c + 1) & 1); CP_WAIT1(); }
        else             { CP_WAIT0(); }
        __syncthreads();

        const uint32_t S  = sb + (uint32_t)(c & 1) * STAGE_B;
        const uint32_t Sa = S, Sb = S + BUFA_B;

        #pragma unroll
        for (int ks = 0; ks < CHK / 16; ks++) {
            const int k0 = ks * 16;
            uint32_t af[2][4], bf[4][2];
            #pragma unroll
            for (int mi = 0; mi < 2; mi++) {
                const uint32_t ro = (uint32_t)((wm * 32 + mi * 16 + arow) * STRIDE + (k0 + acol) * 2);
                ldm_x4(af[mi], Sa + ro);
            }
            #pragma unroll
            for (int np = 0; np < 2; np++) {   // ni pairs (0,1) and (2,3)
                const uint32_t ro = (uint32_t)((wn * 32 + np * 16 + bro) * STRIDE + (k0 + bkc) * 2);
                ldm_x4(&bf[np * 2][0], Sb + ro);
            }
            #pragma unroll
            for (int mi = 0; mi < 2; mi++)
                #pragma unroll
                for (int ni = 0; ni < 4; ni++)
                    mma_f16(acc[mi][ni], af[mi], bf[ni]);
        }
        __syncthreads();
    }

    // ---- epilogue ----
    int liA[4], ljB[8];
    #pragma unroll
    for (int mi = 0; mi < 2; mi++) {
        liA[mi * 2]     = La[wm * 32 + mi * 16 + (lane >> 2)];
        liA[mi * 2 + 1] = La[wm * 32 + mi * 16 + (lane >> 2) + 8];
    }
    #pragma unroll
    for (int ni = 0; ni < 4; ni++) {
        ljB[ni * 2]     = Lb[wn * 32 + ni * 8 + (lane & 3) * 2];
        ljB[ni * 2 + 1] = Lb[wn * 32 + ni * 8 + (lane & 3) * 2 + 1];
    }

    float mp = -CUDART_INF_F, sp = 0.f;
    float ns0 = 0.f, ns1 = 0.f, ns2 = 0.f, ns3 = 0.f;

    if (!straddle) {
        // FAST path (97% of tiles): strictly-upper tile, weight 2.
        #pragma unroll
        for (int mi = 0; mi < 2; mi++)
            #pragma unroll
            for (int ni = 0; ni < 4; ni++)
                #pragma unroll
                for (int e = 0; e < 4; e++) {
                    const float s = acc[mi][ni][e];
                    const bool pos = (liA[mi * 2 + (e >> 1)] == ljB[ni * 2 + (e & 1)]);
                    const float tt = fmaxf(s, -OPT_N);
                    const float en = ex2f(fmaf(tt * C2_LOG2, tt, -D16_LOG2));
                    if (!pos) {
                        if      (e == 0) ns0 += en;
                        else if (e == 1) ns1 += en;
                        else if (e == 2) ns2 += en;
                        else             ns3 += en;
                    } else {
                        const float lp = -GAMMA * fmaxf(OPT_P - s, 0.f) * (s - DELTA_P);
                        if (lp > mp) { sp = sp * __expf(mp - lp) + 1.f; mp = lp; }
                        else         { sp += __expf(lp - mp); }
                    }
                }
    } else {
        // STRADDLE path (3%): include only col > row (strict upper), weight 2.
        #pragma unroll
        for (int mi = 0; mi < 2; mi++)
            #pragma unroll
            for (int ni = 0; ni < 4; ni++)
                #pragma unroll
                for (int e = 0; e < 4; e++) {
                    const int row = rowBase + wm * 32 + mi * 16 + (lane >> 2) + (e >> 1) * 8;
                    const int col = colBase + wn * 32 + ni * 8 + (lane & 3) * 2 + (e & 1);
                    if (col <= row) continue;
                    const float s = acc[mi][ni][e];
                    const bool pos = (liA[mi * 2 + (e >> 1)] == ljB[ni * 2 + (e & 1)]);
                    const float tt = fmaxf(s, -OPT_N);
                    const float en = ex2f(fmaf(tt * C2_LOG2, tt, -D16_LOG2));
                    if (!pos) {
                        ns0 += en;
                    } else {
                        const float lp = -GAMMA * fmaxf(OPT_P - s, 0.f) * (s - DELTA_P);
                        if (lp > mp) { sp = sp * __expf(mp - lp) + 1.f; mp = lp; }
                        else         { sp += __expf(lp - mp); }
                    }
                }
    }

    sp *= 2.0f;
    float mn = 0.f;
    float sn = ((ns0 + ns1) + (ns2 + ns3)) * 2.0f;

    // warp shuffle LSE reduction
    #pragma unroll
    for (int o = 16; o > 0; o >>= 1) {
        const float mp2 = __shfl_xor_sync(0xffffffffu, mp, o);
        const float sp2 = __shfl_xor_sync(0xffffffffu, sp, o);
        const float mn2 = __shfl_xor_sync(0xffffffffu, mn, o);
        const float sn2 = __shfl_xor_sync(0xffffffffu, sn, o);
        lse_combine(mp, sp, mp2, sp2);
        lse_combine(mn, sn, mn2, sn2);
    }
    if (lane == 0) {
        wred[wid][0] = mp; wred[wid][1] = sp;
        wred[wid][2] = mn; wred[wid][3] = sn;
    }
    __syncthreads();
    if (tid == 0) {
        float Mp = wred[0][0], Sp = wred[0][1], Mn = wred[0][2], Sn = wred[0][3];
        #pragma unroll
        for (int w = 1; w < 8; w++) {
            lse_combine(Mp, Sp, wred[w][0], wred[w][1]);
            lse_combine(Mn, Sn, wred[w][2], wred[w][3]);
        }
        const int bid = blockIdx.x;
        g_part[bid * 4 + 0] = Mp; g_part[bid * 4 + 1] = Sp;
        g_part[bid * 4 + 2] = Mn; g_part[bid * 4 + 3] = Sn;
    }
}

// ---------------------------------------------------------------------------
// Kernel 3: combine partials, softplus, write scalar. 512 threads, shuffle-first.
// ---------------------------------------------------------------------------
__global__ void finalize_kernel(float* __restrict__ out, int nPart) {
    const int tid  = threadIdx.x;
    const int wid  = tid >> 5;
    const int lane = tid & 31;
    __shared__ float wred[16][4];

    float mp = -CUDART_INF_F, sp = 0.f, mn = -CUDART_INF_F, sn = 0.f;
    for (int i = tid; i < nPart; i += 512) {
        const float4 v = *(const float4*)(g_part + i * 4);
        lse_combine(mp, sp, v.x, v.y);
        lse_combine(mn, sn, v.z, v.w);
    }
    #pragma unroll
    for (int o = 16; o > 0; o >>= 1) {
        const float m2 = __shfl_xor_sync(0xffffffffu, mp, o);
        const float s2 = __shfl_xor_sync(0xffffffffu, sp, o);
        const float m3 = __shfl_xor_sync(0xffffffffu, mn, o);
        const float s3 = __shfl_xor_sync(0xffffffffu, sn, o);
        lse_combine(mp, sp, m2, s2);
        lse_combine(mn, sn, m3, s3);
    }
    if (lane == 0) {
        wred[wid][0] = mp; wred[wid][1] = sp;
        wred[wid][2] = mn; wred[wid][3] = sn;
    }
    __syncthreads();
    if (tid == 0) {
        float Mp = wred[0][0], Sp = wred[0][1], Mn = wred[0][2], Sn = wred[0][3];
        #pragma unroll
        for (int w = 1; w < 16; w++) {
            lse_combine(Mp, Sp, wred[w][0], wred[w][1]);
            lse_combine(Mn, Sn, wred[w][2], wred[w][3]);
        }
        const float x = (Mp + logf(Sp)) + (Mn + logf(Sn));
        out[0] = (x > 20.f) ? x : log1pf(expf(x));
    }
}

// ---------------------------------------------------------------------------
extern "C" void kernel_launch(void* const* d_in, const int* in_sizes, int n_in,
                              void* d_out, int out_size) {
    const float* emb    = (const float*)d_in[0];
    const int*   labels = (const int*)d_in[1];
    float*       out    = (float*)d_out;

    const int B = in_sizes[1];            // 8192
    const int dyn = 2 * STAGE_B;          // 55296 bytes

    cudaFuncSetAttribute(circle_tile_hmma, cudaFuncAttributeMaxDynamicSharedMemorySize, dyn);

    normalize_kernel<<<B / 16, 256>>>(emb);
    circle_tile_hmma<<<NTILES, NTHREADS, dyn>>>(labels);
    finalize_kernel<<<1, 512>>>(out, NTILES);
}

// round 17
// speedup vs baseline: 1.1822x; 1.0025x over previous
#include <cuda_runtime.h>
#include <cuda_fp16.h>
#include <math.h>
#include <math_constants.h>
#include <stdint.h>

// ---------------------------------------------------------------------------
// CircleLoss round 16: resubmit of R15 (infra failure, no data last round).
//   Tile kernel at 4 CTAs/SM (occupancy experiment): cyc/MMA-instr fell
//   38.8 -> 28.8 -> 23.0 with warps/SMSP 2 -> 4 -> 6; trying 8.
//   smem 4x~56KB = 225KB fits; regs must fit 64/thread.
// ---------------------------------------------------------------------------

#define N_MAX    8192
#define D_DIM    256
#define BM       64                    // tile rows (A)
#define BN       128                   // tile cols (B)
#define NBJ      (N_MAX / BN)          // 64 col blocks
#define NTILES   (NBJ * (NBJ + 1))     // 4160
#define NTHREADS 256
#define CHK      64                    // K-chunk (fp16 elems)
#define NCH      (D_DIM / CHK)         // 4
#define STRIDE   144                   // smem row stride bytes (128 + 16 pad)
#define BUFA_B   (BM * STRIDE)         // 9216
#define BUFB_B   (BN * STRIDE)         // 18432
#define STAGE_B  (BUFA_B + BUFB_B)     // 27648
#define GAMMA    256.0f
#define DELTA_P  0.75f
#define OPT_P    1.25f
#define OPT_N    0.25f
// log2-domain constants for the negative logit: gamma*(s^2 - 1/16) * log2(e)
#define C2_LOG2  369.32993046757263f   // 256 * log2(e)
#define D16_LOG2 23.083120654223289f   // 16  * log2(e)

__device__ __half g_xh[(size_t)N_MAX * D_DIM];   // 4 MB fp16 normalized
__device__ float  g_part[NTILES * 4];

__device__ __forceinline__ uint32_t smem_u32(const void* p) {
    uint32_t a;
    asm("{ .reg .u64 t; cvta.to.shared.u64 t, %1; cvt.u32.u64 %0, t; }" : "=r"(a) : "l"(p));
    return a;
}
__device__ __forceinline__ void ldm_x4(uint32_t* f, uint32_t addr) {
    asm volatile("ldmatrix.sync.aligned.m8n8.x4.shared.b16 {%0,%1,%2,%3}, [%4];"
                 : "=r"(f[0]), "=r"(f[1]), "=r"(f[2]), "=r"(f[3]) : "r"(addr));
}
__device__ __forceinline__ void mma_f16(float* d, const uint32_t* a, const uint32_t* b) {
    asm volatile("mma.sync.aligned.m16n8k16.row.col.f32.f16.f16.f32 "
                 "{%0,%1,%2,%3}, {%4,%5,%6,%7}, {%8,%9}, {%0,%1,%2,%3};"
                 : "+f"(d[0]), "+f"(d[1]), "+f"(d[2]), "+f"(d[3])
                 : "r"(a[0]), "r"(a[1]), "r"(a[2]), "r"(a[3]), "r"(b[0]), "r"(b[1]));
}
__device__ __forceinline__ float ex2f(float x) {
    float r;
    asm("ex2.approx.f32 %0, %1;" : "=f"(r) : "f"(x));
    return r;
}
__device__ __forceinline__ void cpasync16(uint32_t saddr, const void* g) {
    asm volatile("cp.async.cg.shared.global [%0], [%1], 16;" :: "r"(saddr), "l"(g) : "memory");
}
#define CP_COMMIT() asm volatile("cp.async.commit_group;" ::: "memory")
#define CP_WAIT1()  asm volatile("cp.async.wait_group 1;" ::: "memory")
#define CP_WAIT0()  asm volatile("cp.async.wait_group 0;" ::: "memory")

// ---------------------------------------------------------------------------
// Kernel 1: L2-normalize + fp16 convert. One warp per row, 8 rows/block.
// ---------------------------------------------------------------------------
__global__ void normalize_kernel(const float* __restrict__ e) {
    const int wid  = threadIdx.x >> 5;
    const int lane = threadIdx.x & 31;
    const int row  = blockIdx.x * 8 + wid;
    const float4* rp = (const float4*)(e + (size_t)row * D_DIM);
    const float4 v0 = rp[lane * 2];
    const float4 v1 = rp[lane * 2 + 1];
    float ss = v0.x * v0.x + v0.y * v0.y + v0.z * v0.z + v0.w * v0.w
             + v1.x * v1.x + v1.y * v1.y + v1.z * v1.z + v1.w * v1.w;
    #pragma unroll
    for (int o = 16; o > 0; o >>= 1) ss += __shfl_xor_sync(0xffffffffu, ss, o);
    const float inv = 1.0f / fmaxf(sqrtf(ss), 1e-12f);
    __half2 h[4];
    h[0] = __floats2half2_rn(v0.x * inv, v0.y * inv);
    h[1] = __floats2half2_rn(v0.z * inv, v0.w * inv);
    h[2] = __floats2half2_rn(v1.x * inv, v1.y * inv);
    h[3] = __floats2half2_rn(v1.z * inv, v1.w * inv);
    *(uint4*)(g_xh + (size_t)row * D_DIM + lane * 8) = *(const uint4*)h;
}

__device__ __forceinline__ void lse_combine(float& m, float& s, float m2, float s2) {
    const float M = fmaxf(m, m2);
    if (M == -CUDART_INF_F) return;
    s = s * __expf(m - M) + s2 * __expf(m2 - M);
    m = M;
}

// ---------------------------------------------------------------------------
// Kernel 2: one 64x128 tile; 8 warps (2x4), warp tile 32x32.
// fp32-acc fp16 MMA; cp.async double-buffered; 4 CTAs/SM (experiment).
// ---------------------------------------------------------------------------
__global__ __launch_bounds__(NTHREADS, 4)
void circle_tile_hmma(const int* __restrict__ labels) {
    extern __shared__ char dsm[];
    __shared__ int   La[BM];
    __shared__ int   Lb[BN];
    __shared__ float wred[8][4];       // per-warp (mp,sp,mn,sn)

    const int tid  = threadIdx.x;
    const int wid  = tid >> 5;
    const int lane = tid & 31;
    const int wm   = wid & 1;          // 2 warp rows x 32
    const int wn   = wid >> 1;         // 4 warp cols x 32

    const uint32_t sb = smem_u32(dsm);

    // tile id -> (j, i):  id = j*(j+1) + i,  0 <= i <= 2j+1
    const int id = blockIdx.x;
    int j = (int)((sqrtf(4.f * (float)id + 1.f) - 1.f) * 0.5f);
    while (j * (j + 1) > id) j--;
    while ((j + 1) * (j + 2) <= id) j++;
    const int i = id - j * (j + 1);
    const bool straddle = (i >= 2 * j);          // tile touches the diagonal
    const int rowBase = i * BM, colBase = j * BN;

    if (tid < BM)            La[tid]       = labels[rowBase + tid];
    else if (tid < BM + BN)  Lb[tid - BM]  = labels[colBase + (tid - BM)];

    float acc[2][4][4];
    #pragma unroll
    for (int mi = 0; mi < 2; mi++)
        #pragma unroll
        for (int ni = 0; ni < 4; ni++)
            #pragma unroll
            for (int e = 0; e < 4; e++) acc[mi][ni][e] = 0.f;

    // stage chunk c: A = 64 rows (512 segs), B = 128 rows (1024 segs)
    auto stage = [&](int c, int sbuf) {
        const uint32_t base = sb + (uint32_t)sbuf * STAGE_B;
        #pragma unroll
        for (int it = 0; it < 6; it++) {
            const int idx = tid + it * NTHREADS;   // 0..1535
            int r, seg, grow;
            uint32_t dst;
            if (idx < 512) {
                r = idx >> 3; seg = idx & 7;
                grow = rowBase + r;
                dst = base + (uint32_t)(r * STRIDE + seg * 16);
            } else {
                const int v = idx - 512;
                r = v >> 3; seg = v & 7;
                grow = colBase + r;
                dst = base + BUFA_B + (uint32_t)(r * STRIDE + seg * 16);
            }
            const __half* gp = g_xh + (size_t)grow * D_DIM + c * CHK + seg * 8;
            cpasync16(dst, gp);
        }
        CP_COMMIT();
    };

    const int arow = (lane & 7) + ((lane >> 3) & 1) * 8;
    const int acol = (lane >> 4) * 8;
    // B x4 mapping: lanes 0-15 -> n 0-7 (k 0/8), lanes 16-31 -> n 8-15
    const int bro  = ((lane >> 4) & 1) * 8 + (lane & 7);
    const int bkc  = ((lane >> 3) & 1) * 8;

    stage(0, 0);
    for (int c = 0; c < NCH; c++) {
        if (c < NCH - 1) { stage(c + 1, (c + 1) & 1); CP_WAIT1(); }
        else             { CP_WAIT0(); }
        __syncthreads();

        const uint32_t S  = sb + (uint32_t)(c & 1) * STAGE_B;
        const uint32_t Sa = S, Sb = S + BUFA_B;

        #pragma unroll
        for (int ks = 0; ks < CHK / 16; ks++) {
            const int k0 = ks * 16;
            uint32_t af[2][4], bf[4][2];
            #pragma unroll
            for (int mi = 0; mi < 2; mi++) {
                const uint32_t ro = (uint32_t)((wm * 32 + mi * 16 + arow) * STRIDE + (k0 + acol) * 2);
                ldm_x4(af[mi], Sa + ro);
            }
            #pragma unroll
            for (int np = 0; np < 2; np++) {   // ni pairs (0,1) and (2,3)
                const uint32_t ro = (uint32_t)((wn * 32 + np * 16 + bro) * STRIDE + (k0 + bkc) * 2);
                ldm_x4(&bf[np * 2][0], Sb + ro);
            }
            #pragma unroll
            for (int mi = 0; mi < 2; mi++)
                #pragma unroll
                for (int ni = 0; ni < 4; ni++)
                    mma_f16(acc[mi][ni], af[mi], bf[ni]);
        }
        __syncthreads();
    }

    // ---- epilogue ----
    int liA[4], ljB[8];
    #pragma unroll
    for (int mi = 0; mi < 2; mi++) {
        liA[mi * 2]     = La[wm * 32 + mi * 16 + (lane >> 2)];
        liA[mi * 2 + 1] = La[wm * 32 + mi * 16 + (lane >> 2) + 8];
    }
    #pragma unroll
    for (int ni = 0; ni < 4; ni++) {
        ljB[ni * 2]     = Lb[wn * 32 + ni * 8 + (lane & 3) * 2];
        ljB[ni * 2 + 1] = Lb[wn * 32 + ni * 8 + (lane & 3) * 2 + 1];
    }

    float mp = -CUDART_INF_F, sp = 0.f;
    float ns0 = 0.f, ns1 = 0.f, ns2 = 0.f, ns3 = 0.f;

    if (!straddle) {
        // FAST path (97% of tiles): strictly-upper tile, weight 2.
        #pragma unroll
        for (int mi = 0; mi < 2; mi++)
            #pragma unroll
            for (int ni = 0; ni < 4; ni++)
                #pragma unroll
                for (int e = 0; e < 4; e++) {
                    const float s = acc[mi][ni][e];
                    const bool pos = (liA[mi * 2 + (e >> 1)] == ljB[ni * 2 + (e & 1)]);
                    const float tt = fmaxf(s, -OPT_N);
                    const float en = ex2f(fmaf(tt * C2_LOG2, tt, -D16_LOG2));
                    if (!pos) {
                        if      (e == 0) ns0 += en;
                        else if (e == 1) ns1 += en;
                        else if (e == 2) ns2 += en;
                        else             ns3 += en;
                    } else {
                        const float lp = -GAMMA * fmaxf(OPT_P - s, 0.f) * (s - DELTA_P);
                        if (lp > mp) { sp = sp * __expf(mp - lp) + 1.f; mp = lp; }
                        else         { sp += __expf(lp - mp); }
                    }
                }
    } else {
        // STRADDLE path (3%): include only col > row (strict upper), weight 2.
        #pragma unroll
        for (int mi = 0; mi < 2; mi++)
            #pragma unroll
            for (int ni = 0; ni < 4; ni++)
                #pragma unroll
                for (int e = 0; e < 4; e++) {
                    const int row = rowBase + wm * 32 + mi * 16 + (lane >> 2) + (e >> 1) * 8;
                    const int col = colBase + wn * 32 + ni * 8 + (lane & 3) * 2 + (e & 1);
                    if (col <= row) continue;
                    const float s = acc[mi][ni][e];
                    const bool pos = (liA[mi * 2 + (e >> 1)] == ljB[ni * 2 + (e & 1)]);
                    const float tt = fmaxf(s, -OPT_N);
                    const float en = ex2f(fmaf(tt * C2_LOG2, tt, -D16_LOG2));
                    if (!pos) {
                        ns0 += en;
                    } else {
                        const float lp = -GAMMA * fmaxf(OPT_P - s, 0.f) * (s - DELTA_P);
                        if (lp > mp) { sp = sp * __expf(mp - lp) + 1.f; mp = lp; }
                        else         { sp += __expf(lp - mp); }
                    }
                }
    }

    sp *= 2.0f;
    float mn = 0.f;
    float sn = ((ns0 + ns1) + (ns2 + ns3)) * 2.0f;

    // warp shuffle LSE reduction
    #pragma unroll
    for (int o = 16; o > 0; o >>= 1) {
        const float mp2 = __shfl_xor_sync(0xffffffffu, mp, o);
        const float sp2 = __shfl_xor_sync(0xffffffffu, sp, o);
        const float mn2 = __shfl_xor_sync(0xffffffffu, mn, o);
        const float sn2 = __shfl_xor_sync(0xffffffffu, sn, o);
        lse_combine(mp, sp, mp2, sp2);
        lse_combine(mn, sn, mn2, sn2);
    }
    if (lane == 0) {
        wred[wid][0] = mp; wred[wid][1] = sp;
        wred[wid][2] = mn; wred[wid][3] = sn;
    }
    __syncthreads();
    if (tid == 0) {
        float Mp = wred[0][0], Sp = wred[0][1], Mn = wred[0][2], Sn = wred[0][3];
        #pragma unroll
        for (int w = 1; w < 8; w++) {
            lse_combine(Mp, Sp, wred[w][0], wred[w][1]);
            lse_combine(Mn, Sn, wred[w][2], wred[w][3]);
        }
        const int bid = blockIdx.x;
        g_part[bid * 4 + 0] = Mp; g_part[bid * 4 + 1] = Sp;
        g_part[bid * 4 + 2] = Mn; g_part[bid * 4 + 3] = Sn;
    }
}

// ---------------------------------------------------------------------------
// Kernel 3: combine partials, softplus, write scalar. 512 threads, shuffle-first.
// ---------------------------------------------------------------------------
__global__ void finalize_kernel(float* __restrict__ out, int nPart) {
    const int tid  = threadIdx.x;
    const int wid  = tid >> 5;
    const int lane = tid & 31;
    __shared__ float wred[16][4];

    float mp = -CUDART_INF_F, sp = 0.f, mn = -CUDART_INF_F, sn = 0.f;
    for (int i = tid; i < nPart; i += 512) {
        const float4 v = *(const float4*)(g_part + i * 4);
        lse_combine(mp, sp, v.x, v.y);
        lse_combine(mn, sn, v.z, v.w);
    }
    #pragma unroll
    for (int o = 16; o > 0; o >>= 1) {
        const float m2 = __shfl_xor_sync(0xffffffffu, mp, o);
        const float s2 = __shfl_xor_sync(0xffffffffu, sp, o);
        const float m3 = __shfl_xor_sync(0xffffffffu, mn, o);
        const float s3 = __shfl_xor_sync(0xffffffffu, sn, o);
        lse_combine(mp, sp, m2, s2);
        lse_combine(mn, sn, m3, s3);
    }
    if (lane == 0) {
        wred[wid][0] = mp; wred[wid][1] = sp;
        wred[wid][2] = mn; wred[wid][3] = sn;
    }
    __syncthreads();
    if (tid == 0) {
        float Mp = wred[0][0], Sp = wred[0][1], Mn = wred[0][2], Sn = wred[0][3];
        #pragma unroll
        for (int w = 1; w < 16; w++) {
            lse_combine(Mp, Sp, wred[w][0], wred[w][1]);
            lse_combine(Mn, Sn, wred[w][2], wred[w][3]);
        }
        const float x = (Mp + logf(Sp)) + (Mn + logf(Sn));
        out[0] = (x > 20.f) ? x : log1pf(expf(x));
    }
}

// ---------------------------------------------------------------------------
extern "C" void kernel_launch(void* const* d_in, const int* in_sizes, int n_in,
                              void* d_out, int out_size) {
    const float* emb    = (const float*)d_in[0];
    const int*   labels = (const int*)d_in[1];
    float*       out    = (float*)d_out;

    const int B = in_sizes[1];            // 8192
    const int dyn = 2 * STAGE_B;          // 55296 bytes

    cudaFuncSetAttribute(circle_tile_hmma, cudaFuncAttributeMaxDynamicSharedMemorySize, dyn);

    normalize_kernel<<<B / 8, 256>>>(emb);
    circle_tile_hmma<<<NTILES, NTHREADS, dyn>>>(labels);
    finalize_kernel<<<1, 512>>>(out, NTILES);
}